// round 14
// baseline (speedup 1.0000x reference)
#include <cuda_runtime.h>
#include <cuda_bf16.h>
#include <cstdint>
#include <math.h>

// Dims fixed by the reference
#define BB 1024
#define KK 256
#define DD 1024
#define PP 768

typedef __nv_bfloat16 bf16;

// ---------------- scratch (device globals; no allocs allowed) ----------------
__device__ bf16  g_jh [BB * DD];       // joint (bf16)              [1024,1024]
__device__ bf16  g_ch [KK * DD];       // conf  (bf16)              [256,1024]
__device__ bf16  g_wqh[DD * PP];       // Wq (bf16, natural [D,P])  [1024,768]
__device__ bf16  g_wkh[DD * PP];       // Wk (bf16, natural [D,P])  [1024,768]
__device__ bf16  g_cp2[KK * DD];       // conf*prior (bf16, [K,D])  [256,1024]
__device__ bf16  g_qh [BB * PP];       // q (bf16)                  [1024,768]
__device__ bf16  g_kh [KK * PP];       // k (bf16)                  [256,768]
__device__ float g_s  [4 * BB * KK];   // score partials (fp32) x4  [4,1024,256]
__device__ bf16  g_ah [BB * KK];       // attn (bf16)               [1024,256]

// ---------------- helpers ----------------------------------------------------
__device__ __forceinline__ uint32_t smem_u32(const void* p) {
    uint32_t a;
    asm("{ .reg .u64 t; cvta.to.shared.u64 t, %1; cvt.u32.u64 %0, t; }"
        : "=r"(a) : "l"(p));
    return a;
}

#define SWZ(off) ((off) ^ (((off) >> 3) & 0x70))

__device__ __forceinline__ void cp_async16(uint32_t dst, const void* src) {
    asm volatile("cp.async.cg.shared.global [%0], [%1], 16;"
                 :: "r"(dst), "l"(src));
}
#define CP_COMMIT() asm volatile("cp.async.commit_group;" ::: "memory")

__device__ __forceinline__ void ldm_x4(uint32_t* r, uint32_t addr) {
    asm volatile("ldmatrix.sync.aligned.m8n8.x4.shared.b16 {%0,%1,%2,%3}, [%4];"
                 : "=r"(r[0]), "=r"(r[1]), "=r"(r[2]), "=r"(r[3]) : "r"(addr));
}

__device__ __forceinline__ void ldm_x4_t(uint32_t* r, uint32_t addr) {
    asm volatile("ldmatrix.sync.aligned.m8n8.x4.trans.shared.b16 {%0,%1,%2,%3}, [%4];"
                 : "=r"(r[0]), "=r"(r[1]), "=r"(r[2]), "=r"(r[3]) : "r"(addr));
}

__device__ __forceinline__ void mma16816(float* c, const uint32_t* a,
                                         uint32_t b0, uint32_t b1) {
    asm volatile(
        "mma.sync.aligned.m16n8k16.row.col.f32.bf16.bf16.f32 "
        "{%0,%1,%2,%3}, {%4,%5,%6,%7}, {%8,%9}, {%0,%1,%2,%3};"
        : "+f"(c[0]), "+f"(c[1]), "+f"(c[2]), "+f"(c[3])
        : "r"(a[0]), "r"(a[1]), "r"(a[2]), "r"(a[3]), "r"(b0), "r"(b1));
}

// ---------------------------------------------------------------------------
// Core bf16 tensor-core GEMM tile (identical to the 25.1us R11 version)
// ---------------------------------------------------------------------------
#define EPI_BF16  0
#define EPI_SCALE 1
#define EPI_ADD   2
#define STAGE_BYTES 16384  // 8KB A + 8KB B

template <int EPI, int BTRANS>
__device__ __forceinline__ void gemm_core(
    const bf16* __restrict__ A, const bf16* __restrict__ B,
    const float* __restrict__ Cadd, void* __restrict__ Cout,
    int row0, int col0, int Ka, int ldb, int Nout, int nchunk, int koff,
    float alpha)
{
    extern __shared__ char smem[];
    const uint32_t sb = smem_u32(smem);
    const int tid  = threadIdx.x;
    const int wid  = tid >> 5, lane = tid & 31;
    const int wm   = wid & 1;
    const int wn   = wid >> 1;

    const int g  = lane >> 3;
    const int l8 = lane & 7;

    const int a_row  = wm * 32 + (g & 1) * 8 + l8;
    const int a_koff = (g >> 1) * 8;
    const int bt_row  = wn * 32 + (g >> 1) * 8 + l8;
    const int bt_koff = (g & 1) * 8;
    const int bn_krow = (g & 1) * 8 + l8;
    const int bn_col  = wn * 32 + (g >> 1) * 8;

    float acc[2][4][4];
    #pragma unroll
    for (int mi = 0; mi < 2; mi++)
        #pragma unroll
        for (int ni = 0; ni < 4; ni++)
            #pragma unroll
            for (int j = 0; j < 4; j++) acc[mi][ni][j] = 0.f;

    auto load_chunk = [&](int c, int buf) {
        const uint32_t st = sb + buf * STAGE_BYTES;
        const bf16* gA = A + (size_t)row0 * Ka + koff + c * 64;
        #pragma unroll
        for (int i = 0; i < 4; i++) {
            int s = tid + i * 128;
            int r = s >> 3, ks = s & 7;
            uint32_t off = SWZ((uint32_t)(r * 128 + ks * 16));
            cp_async16(st + off, gA + (size_t)r * Ka + ks * 8);
        }
        #pragma unroll
        for (int i = 0; i < 4; i++) {
            int s = tid + i * 128;
            int r = s >> 3, ks = s & 7;
            uint32_t off = SWZ((uint32_t)(r * 128 + ks * 16));
            const bf16* src = BTRANS
                ? B + (size_t)(col0 + r) * Ka + koff + c * 64 + ks * 8
                : B + (size_t)(koff + c * 64 + r) * ldb + col0 + ks * 8;
            cp_async16(st + 8192 + off, src);
        }
        CP_COMMIT();
    };

    auto load_frags = [&](uint32_t stA, uint32_t stB, int kb,
                          uint32_t (*fa)[4], uint32_t (*fb)[4]) {
        #pragma unroll
        for (int mi = 0; mi < 2; mi++)
            ldm_x4(fa[mi], stA + SWZ((uint32_t)((a_row + mi * 16) * 128 +
                                                (kb + a_koff) * 2)));
        #pragma unroll
        for (int pi = 0; pi < 2; pi++) {
            if (BTRANS)
                ldm_x4(fb[pi], stB + SWZ((uint32_t)((bt_row + pi * 16) * 128 +
                                                    (kb + bt_koff) * 2)));
            else
                ldm_x4_t(fb[pi], stB + SWZ((uint32_t)((kb + bn_krow) * 128 +
                                                      (bn_col + pi * 16) * 2)));
        }
    };

    load_chunk(0, 0);

    for (int c = 0; c < nchunk; c++) {
        const int buf = c & 1;
        if (c + 1 < nchunk) {
            load_chunk(c + 1, buf ^ 1);
            asm volatile("cp.async.wait_group 1;" ::: "memory");
        } else {
            asm volatile("cp.async.wait_group 0;" ::: "memory");
        }
        __syncthreads();

        const uint32_t stA = sb + buf * STAGE_BYTES;
        const uint32_t stB = stA + 8192;

        uint32_t fa[2][2][4], fb[2][2][4];
        load_frags(stA, stB, 0, fa[0], fb[0]);
        #pragma unroll
        for (int k16 = 0; k16 < 4; k16++) {
            const int cur = k16 & 1, nxt = cur ^ 1;
            if (k16 < 3)
                load_frags(stA, stB, (k16 + 1) * 16, fa[nxt], fb[nxt]);
            #pragma unroll
            for (int mi = 0; mi < 2; mi++)
                #pragma unroll
                for (int ni = 0; ni < 4; ni++)
                    mma16816(acc[mi][ni], fa[cur][mi],
                             fb[cur][ni >> 1][(ni & 1) * 2],
                             fb[cur][ni >> 1][(ni & 1) * 2 + 1]);
        }
        __syncthreads();
    }

    const int grp = lane >> 2, tig = lane & 3;
    const int rbase = row0 + wm * 32 + grp;
    const int cbase = col0 + wn * 32 + tig * 2;
    #pragma unroll
    for (int mi = 0; mi < 2; mi++) {
        #pragma unroll
        for (int ni = 0; ni < 4; ni++) {
            const int cc = cbase + ni * 8;
            const int r1 = rbase + mi * 16, r2 = r1 + 8;
            float* f = acc[mi][ni];
            if (EPI == EPI_BF16) {
                bf16* o = (bf16*)Cout;
                *(__nv_bfloat162*)&o[(size_t)r1 * Nout + cc] =
                    __floats2bfloat162_rn(f[0], f[1]);
                *(__nv_bfloat162*)&o[(size_t)r2 * Nout + cc] =
                    __floats2bfloat162_rn(f[2], f[3]);
            } else if (EPI == EPI_SCALE) {
                float* o = (float*)Cout;
                *(float2*)&o[(size_t)r1 * Nout + cc] =
                    make_float2(alpha * f[0], alpha * f[1]);
                *(float2*)&o[(size_t)r2 * Nout + cc] =
                    make_float2(alpha * f[2], alpha * f[3]);
            } else {
                float* o = (float*)Cout;
                float2 x = *(const float2*)&Cadd[(size_t)r1 * Nout + cc];
                float2 y = *(const float2*)&Cadd[(size_t)r2 * Nout + cc];
                *(float2*)&o[(size_t)r1 * Nout + cc] =
                    make_float2(f[0] + x.x, f[1] + x.y);
                *(float2*)&o[(size_t)r2 * Nout + cc] =
                    make_float2(f[2] + y.x, f[3] + y.y);
            }
        }
    }
}

// ---------------------------------------------------------------------------
// GEMM wrappers (identical to the 25.1us R11 version)
// ---------------------------------------------------------------------------
__global__ __launch_bounds__(128) void proj_kernel(
    const bf16* __restrict__ jh, const bf16* __restrict__ wqh,
    const bf16* __restrict__ ch, const bf16* __restrict__ wkh,
    bf16* __restrict__ qh, bf16* __restrict__ kh)
{
    const int bx = blockIdx.x;
    if (bx < 192) {   // q: 16 (M) x 12 (N)
        gemm_core<EPI_BF16, 0>(jh, wqh, nullptr, qh,
                               (bx / 12) * 64, (bx % 12) * 64,
                               DD, PP, PP, DD / 64, 0, 1.f);
    } else {          // k: 4 (M) x 12 (N)
        const int b2 = bx - 192;
        gemm_core<EPI_BF16, 0>(ch, wkh, nullptr, kh,
                               (b2 / 12) * 64, (b2 % 12) * 64,
                               DD, PP, PP, DD / 64, 0, 1.f);
    }
}

__global__ __launch_bounds__(128) void scores_kernel(
    const bf16* __restrict__ qh, const bf16* __restrict__ kh,
    float* __restrict__ s)
{
    const int z = blockIdx.z;
    gemm_core<EPI_SCALE, 1>(qh, kh, nullptr, s + (size_t)z * BB * KK,
                            blockIdx.y * 64, blockIdx.x * 64,
                            PP, PP, KK, 3, z * 192, 1.f / 32.f);
}

__global__ __launch_bounds__(128) void out_kernel(
    const bf16* __restrict__ ah, const bf16* __restrict__ cp2,
    const float* __restrict__ joint, float* __restrict__ out)
{
    gemm_core<EPI_ADD, 0>(ah, cp2, joint, out,
                          blockIdx.y * 64, blockIdx.x * 64,
                          KK, DD, DD, KK / 64, 0, 1.f);
}

// ---------------------------------------------------------------------------
// Fused prep (R11-exact): one float4 per thread, grid = PREP_TOTAL/1024.
// ---------------------------------------------------------------------------
#define N_JOINT (BB * DD)
#define N_CONF  (KK * DD)
#define N_W     (DD * PP)
#define PREP_TOTAL (N_JOINT + N_CONF + 2 * N_W)

__global__ void prep_all(const float* __restrict__ joint,
                         const float* __restrict__ conf,
                         const float* __restrict__ prior,
                         const float* __restrict__ Wq,
                         const float* __restrict__ Wk,
                         bf16* __restrict__ jh, bf16* __restrict__ ch,
                         bf16* __restrict__ cp2,
                         bf16* __restrict__ wqh, bf16* __restrict__ wkh)
{
    int i = (blockIdx.x * blockDim.x + threadIdx.x) * 4;
    if (i < N_JOINT) {
        float4 v = *(const float4*)&joint[i];
        *(__nv_bfloat162*)&jh[i]     = __floats2bfloat162_rn(v.x, v.y);
        *(__nv_bfloat162*)&jh[i + 2] = __floats2bfloat162_rn(v.z, v.w);
    } else if (i < N_JOINT + N_CONF) {
        int idx = i - N_JOINT;
        float4 v = *(const float4*)&conf[idx];
        *(__nv_bfloat162*)&ch[idx]     = __floats2bfloat162_rn(v.x, v.y);
        *(__nv_bfloat162*)&ch[idx + 2] = __floats2bfloat162_rn(v.z, v.w);
        float p = prior[idx >> 10];
        *(__nv_bfloat162*)&cp2[idx]     = __floats2bfloat162_rn(v.x * p, v.y * p);
        *(__nv_bfloat162*)&cp2[idx + 2] = __floats2bfloat162_rn(v.z * p, v.w * p);
    } else if (i < N_JOINT + N_CONF + N_W) {
        int idx = i - N_JOINT - N_CONF;
        float4 v = *(const float4*)&Wq[idx];
        *(__nv_bfloat162*)&wqh[idx]     = __floats2bfloat162_rn(v.x, v.y);
        *(__nv_bfloat162*)&wqh[idx + 2] = __floats2bfloat162_rn(v.z, v.w);
    } else {
        int idx = i - N_JOINT - N_CONF - N_W;
        float4 v = *(const float4*)&Wk[idx];
        *(__nv_bfloat162*)&wkh[idx]     = __floats2bfloat162_rn(v.x, v.y);
        *(__nv_bfloat162*)&wkh[idx + 2] = __floats2bfloat162_rn(v.z, v.w);
    }
}

// ---------------------------------------------------------------------------
// Softmax: 2 rows per warp, chains interleaved. block=128 (4 warps = 8 rows),
// grid = BB/8 = 128. All 16 float4 loads issued before any reduction.
// Per-row math identical to previous rounds (same summation order).
// ---------------------------------------------------------------------------
__global__ __launch_bounds__(128) void softmax_warp2(const float* __restrict__ s,
                                                     bf16* __restrict__ a)
{
    const int wid  = threadIdx.x >> 5;
    const int lane = threadIdx.x & 31;
    const int r0   = blockIdx.x * 8 + wid * 2;   // rows r0, r0+1
    const size_t PSTRIDE = (size_t)BB * KK;

    size_t c0[2], c1[2];
    float4 v0[2], v1[2];
    #pragma unroll
    for (int r = 0; r < 2; r++) {
        c0[r] = (size_t)(r0 + r) * KK + lane * 4;
        c1[r] = c0[r] + 128;
        v0[r] = *(const float4*)&s[c0[r]];
        v1[r] = *(const float4*)&s[c1[r]];
    }
    #pragma unroll
    for (int p = 1; p < 4; p++) {
        #pragma unroll
        for (int r = 0; r < 2; r++) {
            float4 u0 = *(const float4*)&s[c0[r] + p * PSTRIDE];
            float4 u1 = *(const float4*)&s[c1[r] + p * PSTRIDE];
            v0[r].x += u0.x; v0[r].y += u0.y; v0[r].z += u0.z; v0[r].w += u0.w;
            v1[r].x += u1.x; v1[r].y += u1.y; v1[r].z += u1.z; v1[r].w += u1.w;
        }
    }

    // Interleaved max reductions (two independent chains)
    float m[2];
    #pragma unroll
    for (int r = 0; r < 2; r++)
        m[r] = fmaxf(fmaxf(fmaxf(v0[r].x, v0[r].y), fmaxf(v0[r].z, v0[r].w)),
                     fmaxf(fmaxf(v1[r].x, v1[r].y), fmaxf(v1[r].z, v1[r].w)));
    #pragma unroll
    for (int o = 16; o; o >>= 1) {
        #pragma unroll
        for (int r = 0; r < 2; r++)
            m[r] = fmaxf(m[r], __shfl_xor_sync(~0u, m[r], o));
    }

    float e[2][8];
    #pragma unroll
    for (int r = 0; r < 2; r++) {
        e[r][0] = __expf(v0[r].x - m[r]); e[r][1] = __expf(v0[r].y - m[r]);
        e[r][2] = __expf(v0[r].z - m[r]); e[r][3] = __expf(v0[r].w - m[r]);
        e[r][4] = __expf(v1[r].x - m[r]); e[r][5] = __expf(v1[r].y - m[r]);
        e[r][6] = __expf(v1[r].z - m[r]); e[r][7] = __expf(v1[r].w - m[r]);
    }

    float sm[2];
    #pragma unroll
    for (int r = 0; r < 2; r++)
        sm[r] = ((e[r][0] + e[r][1]) + (e[r][2] + e[r][3])) +
                ((e[r][4] + e[r][5]) + (e[r][6] + e[r][7]));
    #pragma unroll
    for (int o = 16; o; o >>= 1) {
        #pragma unroll
        for (int r = 0; r < 2; r++)
            sm[r] += __shfl_xor_sync(~0u, sm[r], o);
    }

    #pragma unroll
    for (int r = 0; r < 2; r++) {
        const float inv = 1.0f / sm[r];
        __nv_bfloat162 o0 = __floats2bfloat162_rn(e[r][0] * inv, e[r][1] * inv);
        __nv_bfloat162 o1 = __floats2bfloat162_rn(e[r][2] * inv, e[r][3] * inv);
        __nv_bfloat162 o2 = __floats2bfloat162_rn(e[r][4] * inv, e[r][5] * inv);
        __nv_bfloat162 o3 = __floats2bfloat162_rn(e[r][6] * inv, e[r][7] * inv);
        *(uint2*)&a[c0[r]] = make_uint2(*(uint32_t*)&o0, *(uint32_t*)&o1);
        *(uint2*)&a[c1[r]] = make_uint2(*(uint32_t*)&o2, *(uint32_t*)&o3);
    }
}

// ---------------------------------------------------------------------------
extern "C" void kernel_launch(void* const* d_in, const int* in_sizes, int n_in,
                              void* d_out, int out_size)
{
    const float* joint = (const float*)d_in[0];   // [1024,1024]
    const float* conf  = (const float*)d_in[1];   // [256,1024]
    const float* prior = (const float*)d_in[2];   // [256,1]
    const float* Wq    = (const float*)d_in[3];   // [1024,768]
    const float* Wk    = (const float*)d_in[4];   // [1024,768]
    float* out = (float*)d_out;                   // [1024,1024]

    bf16 *jh, *ch, *wqh, *wkh, *cp2, *qh, *kh, *ah; float* s;
    cudaGetSymbolAddress((void**)&jh,  g_jh);
    cudaGetSymbolAddress((void**)&ch,  g_ch);
    cudaGetSymbolAddress((void**)&wqh, g_wqh);
    cudaGetSymbolAddress((void**)&wkh, g_wkh);
    cudaGetSymbolAddress((void**)&cp2, g_cp2);
    cudaGetSymbolAddress((void**)&qh,  g_qh);
    cudaGetSymbolAddress((void**)&kh,  g_kh);
    cudaGetSymbolAddress((void**)&s,   g_s);
    cudaGetSymbolAddress((void**)&ah,  g_ah);

    const int SMEM = 2 * STAGE_BYTES;  // 32 KB dynamic

    // 1) prep: fused bf16 convert (R11-exact)
    prep_all<<<PREP_TOTAL / 1024, 256>>>(joint, conf, prior, Wq, Wk,
                                         jh, ch, cp2, wqh, wkh);
    // 2) q-proj + k-proj fused: 240 CTAs
    proj_kernel<<<240, 128, SMEM>>>(jh, wqh, ch, wkh, qh, kh);
    // 3) scores split-K x4: 256 CTAs, fp32 partials
    scores_kernel<<<dim3(KK / 64, BB / 64, 4), 128, SMEM>>>(qh, kh, s);
    // 4) softmax: 2 rows/warp, interleaved chains (128 CTAs)
    softmax_warp2<<<BB / 8, 128>>>(s, ah);
    // 5) out = attn @ (conf*prior) + joint: 256 CTAs
    out_kernel<<<dim3(DD / 64, BB / 64), 128, SMEM>>>(ah, cp2, joint, out);
}